// round 4
// baseline (speedup 1.0000x reference)
#include <cuda_runtime.h>

// ---------------- problem constants ----------------
#define Nn   2048
#define Bb   16
#define Cc   64
#define Tt   12
#define Ee   10
#define Oo   64
#define MC   (Bb*Cc*Tt)        // 12288  columns of node-major matrices
#define NT   (Nn*Tt)           // 24576
#define ONT  (Oo*Nn*Tt)        // 1572864
#define XAV_SIZE (Bb*ONT)      // 25165824 floats = one output tensor

// ---------------- scratch (device globals; no allocation allowed) ----------------
__device__ float g_A [Nn*Nn];          // adaptive adjacency (softmax)
__device__ float g_S2[Nn*Nn];          // 2*A@A - I
__device__ float g_PT[Nn*Nn];          // support transposed
__device__ float g_Xr[(size_t)Nn*MC];  // x reorganized node-major
__device__ float g_G1[(size_t)Nn*MC];  // A  @ Xr
__device__ float g_G2[(size_t)Nn*MC];  // S2 @ Xr
__device__ float g_D1[(size_t)Nn*MC];  // P^T @ Xr
__device__ float g_D2[(size_t)Nn*MC];  // P^T @ D1

// ---------------- f32x2 helpers (FFMA2: 2x fp32 FMA throughput on sm_103a) ----------------
__device__ __forceinline__ unsigned long long pack_dup(float a){
    unsigned long long r;
    asm("mov.b64 %0, {%1, %1};" : "=l"(r) : "f"(a));
    return r;
}
__device__ __forceinline__ void fma2(unsigned long long &acc,
                                     unsigned long long a, unsigned long long b){
    asm("fma.rn.f32x2 %0, %1, %2, %0;" : "+l"(acc) : "l"(a), "l"(b));
}

// ---------------- A = rowsoftmax(relu(E E^T)) ----------------
__global__ __launch_bounds__(256) void compute_A_kernel(const float* __restrict__ emb)
{
    __shared__ float row[Nn];
    __shared__ float red[256];
    const int n = blockIdx.x, tid = threadIdx.x;

    float e[Ee];
#pragma unroll
    for (int d = 0; d < Ee; d++) e[d] = emb[n*Ee + d];

    float lmax = -1e30f;
    for (int m = tid; m < Nn; m += 256){
        float s = 0.f;
#pragma unroll
        for (int d = 0; d < Ee; d++) s += e[d] * emb[m*Ee + d];
        s = fmaxf(s, 0.f);
        row[m] = s;
        lmax = fmaxf(lmax, s);
    }
    red[tid] = lmax; __syncthreads();
    for (int s = 128; s > 0; s >>= 1){
        if (tid < s) red[tid] = fmaxf(red[tid], red[tid+s]);
        __syncthreads();
    }
    const float mx = red[0];
    __syncthreads();

    float lsum = 0.f;
    for (int m = tid; m < Nn; m += 256){
        float v = expf(row[m] - mx);
        row[m] = v;
        lsum += v;
    }
    red[tid] = lsum; __syncthreads();
    for (int s = 128; s > 0; s >>= 1){
        if (tid < s) red[tid] += red[tid+s];
        __syncthreads();
    }
    const float inv = 1.f / red[0];
    for (int m = tid; m < Nn; m += 256)
        g_A[(size_t)n*Nn + m] = row[m] * inv;
}

// ---------------- x[B,C,N,T] -> Xr[N, (b*C+c)*T + t] ----------------
__global__ __launch_bounds__(256) void transpose_X_kernel(const float* __restrict__ x)
{
    int g  = blockIdx.x * 256 + threadIdx.x;   // 0 .. Nn*1024-1
    int n  = g >> 10;
    int bc = g & 1023;
    const float4* src = (const float4*)(x + ((size_t)bc*Nn + n) * Tt);
    float4*       dst = (float4*)(g_Xr + (size_t)n*MC + (size_t)bc*Tt);
    dst[0] = src[0]; dst[1] = src[1]; dst[2] = src[2];
}

// ---------------- PT[w,v] = support[v,w] ----------------
__global__ void transpose_P_kernel(const float* __restrict__ P)
{
    __shared__ float tile[32][33];
    const int x0 = blockIdx.x*32, y0 = blockIdx.y*32;
    const int tx = threadIdx.x, ty = threadIdx.y;   // (32,8)
#pragma unroll
    for (int j = 0; j < 4; j++)
        tile[ty + j*8][tx] = P[(size_t)(y0 + ty + j*8)*Nn + x0 + tx];
    __syncthreads();
#pragma unroll
    for (int j = 0; j < 4; j++)
        g_PT[(size_t)(x0 + ty + j*8)*Nn + y0 + tx] = tile[tx][ty + j*8];
}

// ---------------- fp32 GEMM: C = alpha*(A@B) (+diagAdd on diagonal) ----------------
// Tiles: BM=BN=128, BK=16, 256 threads, 8x8 per thread, f32x2 FFMA2 inner product,
// double-buffered shared with register prefetch. All dims are exact tile multiples.
__global__ __launch_bounds__(256) void gemm_f32(
    int M, int Ncols, int K, float alpha,
    const float* __restrict__ A, const float* __restrict__ B,
    float* __restrict__ C, float diagAdd)
{
    __shared__ __align__(16) float As[2][16][128];
    __shared__ __align__(16) float Bs[2][16][128];
    const int tid = threadIdx.x;
    const int bx = blockIdx.x, by = blockIdx.y;

    const int arow = tid >> 2;           // 0..63
    const int acol = (tid & 3) * 4;      // 0,4,8,12
    const int brow = tid >> 5;           // 0..7
    const int bcol = (tid & 31) * 4;     // 0..124

    const float* Aptr = A + (size_t)(by*128 + arow)*K + acol;
    const float* Bptr = B + (size_t)brow*Ncols + (size_t)bx*128 + bcol;
    const int nk = K >> 4;

    { // tile 0
        float4 a0 = *(const float4*)Aptr;
        float4 a1 = *(const float4*)(Aptr + (size_t)64*K);
        As[0][acol+0][arow]    = a0.x; As[0][acol+1][arow]    = a0.y;
        As[0][acol+2][arow]    = a0.z; As[0][acol+3][arow]    = a0.w;
        As[0][acol+0][arow+64] = a1.x; As[0][acol+1][arow+64] = a1.y;
        As[0][acol+2][arow+64] = a1.z; As[0][acol+3][arow+64] = a1.w;
        *(float4*)&Bs[0][brow  ][bcol] = *(const float4*)Bptr;
        *(float4*)&Bs[0][brow+8][bcol] = *(const float4*)(Bptr + (size_t)8*Ncols);
    }
    __syncthreads();

    const int ty = tid >> 4, tx = tid & 15;
    const int mBase = ty*8, nBase = tx*8;
    unsigned long long accP[8][4];
#pragma unroll
    for (int i = 0; i < 8; i++)
#pragma unroll
        for (int j = 0; j < 4; j++) accP[i][j] = 0ULL;

    for (int kt = 0; kt < nk; kt++){
        const int cur = kt & 1;
        float4 a0n, a1n, b0n, b1n;
        const bool more = (kt + 1 < nk);
        if (more){
            const float* Ap = Aptr + (kt+1)*16;
            a0n = *(const float4*)Ap;
            a1n = *(const float4*)(Ap + (size_t)64*K);
            const float* Bp = Bptr + (size_t)(kt+1)*16*Ncols;
            b0n = *(const float4*)Bp;
            b1n = *(const float4*)(Bp + (size_t)8*Ncols);
        }
#pragma unroll
        for (int kk = 0; kk < 16; kk++){
            float4 a0 = *(const float4*)&As[cur][kk][mBase];
            float4 a1 = *(const float4*)&As[cur][kk][mBase+4];
            const unsigned long long* bsp =
                (const unsigned long long*)&Bs[cur][kk][nBase];
            unsigned long long bp0 = bsp[0], bp1 = bsp[1], bp2 = bsp[2], bp3 = bsp[3];
            float av[8] = {a0.x,a0.y,a0.z,a0.w,a1.x,a1.y,a1.z,a1.w};
#pragma unroll
            for (int i = 0; i < 8; i++){
                unsigned long long ap = pack_dup(av[i]);
                fma2(accP[i][0], ap, bp0);
                fma2(accP[i][1], ap, bp1);
                fma2(accP[i][2], ap, bp2);
                fma2(accP[i][3], ap, bp3);
            }
        }
        if (more){
            const int nxt = cur ^ 1;
            As[nxt][acol+0][arow]    = a0n.x; As[nxt][acol+1][arow]    = a0n.y;
            As[nxt][acol+2][arow]    = a0n.z; As[nxt][acol+3][arow]    = a0n.w;
            As[nxt][acol+0][arow+64] = a1n.x; As[nxt][acol+1][arow+64] = a1n.y;
            As[nxt][acol+2][arow+64] = a1n.z; As[nxt][acol+3][arow+64] = a1n.w;
            *(float4*)&Bs[nxt][brow  ][bcol] = b0n;
            *(float4*)&Bs[nxt][brow+8][bcol] = b1n;
            __syncthreads();
        }
    }

    const int cBase = bx*128 + nBase;
    const int rBase = by*128 + mBase;
#pragma unroll
    for (int i = 0; i < 8; i++){
        const int row = rBase + i;
        float v[8];
#pragma unroll
        for (int j = 0; j < 4; j++){
            float2 f = *reinterpret_cast<float2*>(&accP[i][j]);
            v[2*j]   = f.x * alpha;
            v[2*j+1] = f.y * alpha;
        }
        if (diagAdd != 0.f){
            const int d = row - cBase;
            if (d >= 0 && d < 8) v[d] += diagAdd;
        }
        float4* outp = (float4*)(C + (size_t)row*Ncols + cBase);
        outp[0] = make_float4(v[0], v[1], v[2], v[3]);
        outp[1] = make_float4(v[4], v[5], v[6], v[7]);
    }
}

// ---------------- per-node epilogue ----------------
// mode 0 (x_av):  In = {Xr,G1,G2}[n,:], W_n = sum_d E[n,d]*Wp[d], b_n = E[n,:]@bias_pool
// mode 1 (x_gcn): In = {Xr,D1,D2}[n,:], W = mlp_w, b = mlp_b
// Out[(b,t),o] = sum_{seg,c} In[seg][b*768 + c*12 + t] * W[(seg*64+c)*64 + o] + b[o]
// written at out[b,o,n,t] (mode1 offset by XAV_SIZE).
__global__ __launch_bounds__(256) void epilogue_kernel(
    const float* __restrict__ emb,
    const float* __restrict__ wsrc,    // weights_pool (mode0) or mlp_w (mode1)
    const float* __restrict__ bsrc,    // bias_pool    (mode0) or mlp_b (mode1)
    float* __restrict__ out, int mode)
{
    extern __shared__ float sm[];
    float* sIn = sm;                 // 3*MC
    float* sW  = sm + 3*MC;          // 192*64 = 12288
    float* sB  = sW + 12288;         // 64
    const int n = blockIdx.x, tid = threadIdx.x;

    const float* s0 = g_Xr;
    const float* s1 = (mode == 0) ? g_G1 : g_D1;
    const float* s2 = (mode == 0) ? g_G2 : g_D2;
    const size_t off = (size_t)n * MC;

    for (int i = tid; i < MC/4; i += 256){
        ((float4*)sIn)[i]            = ((const float4*)(s0 + off))[i];
        ((float4*)(sIn +   MC))[i]   = ((const float4*)(s1 + off))[i];
        ((float4*)(sIn + 2*MC))[i]   = ((const float4*)(s2 + off))[i];
    }
    if (mode == 0){
        float e[Ee];
#pragma unroll
        for (int d = 0; d < Ee; d++) e[d] = emb[n*Ee + d];
        for (int i = tid; i < 12288; i += 256){
            float s = 0.f;
#pragma unroll
            for (int d = 0; d < Ee; d++) s += e[d] * wsrc[d*12288 + i];
            sW[i] = s;
        }
        if (tid < Oo){
            float s = 0.f;
#pragma unroll
            for (int d = 0; d < Ee; d++) s += e[d] * bsrc[d*Oo + tid];
            sB[tid] = s;
        }
    } else {
        for (int i = tid; i < 12288; i += 256) sW[i] = wsrc[i];
        if (tid < Oo) sB[tid] = bsrc[tid];
    }
    __syncthreads();

    // rows via tx (coalesced t-runs in stores), cols via ty
    const int ty = tid >> 4, tx = tid & 15;
    const int oBase = ty * 4;
    int offr[12], bArr[12], tArr[12];
#pragma unroll
    for (int i = 0; i < 12; i++){
        int r = tx + 16*i;          // 0..191 = b*12 + t
        int b = r / 12, t = r - b*12;
        offr[i] = b*(Cc*Tt) + t;    // b*768 + t
        bArr[i] = b; tArr[i] = t;
    }

    float acc[12][4];
#pragma unroll
    for (int i = 0; i < 12; i++)
#pragma unroll
        for (int j = 0; j < 4; j++) acc[i][j] = 0.f;

    for (int kc = 0; kc < 192; kc++){
        const int k = kc >> 6;
        const int c = kc & 63;
        const float* src = sIn + k*MC + c*Tt;
        const float w0 = sW[kc*64 + oBase + 0];
        const float w1 = sW[kc*64 + oBase + 1];
        const float w2 = sW[kc*64 + oBase + 2];
        const float w3 = sW[kc*64 + oBase + 3];
#pragma unroll
        for (int i = 0; i < 12; i++){
            float a = src[offr[i]];
            acc[i][0] += a*w0; acc[i][1] += a*w1;
            acc[i][2] += a*w2; acc[i][3] += a*w3;
        }
    }

    float* outBase = out + (mode ? (size_t)XAV_SIZE : 0);
#pragma unroll
    for (int i = 0; i < 12; i++){
        const int b = bArr[i], t = tArr[i];
        const size_t p = (size_t)b*ONT + (size_t)n*Tt + t;
#pragma unroll
        for (int j = 0; j < 4; j++){
            const int o = oBase + j;
            outBase[p + (size_t)o*NT] = acc[i][j] + sB[o];
        }
    }
}

// ---------------- launch ----------------
#define EPI_SMEM ((3*MC + 12288 + 64) * (int)sizeof(float))   // 196,864 B

extern "C" void kernel_launch(void* const* d_in, const int* in_sizes, int n_in,
                              void* d_out, int out_size)
{
    const float* x     = (const float*)d_in[0];
    const float* emb   = (const float*)d_in[1];
    const float* sup   = (const float*)d_in[2];
    const float* wpool = (const float*)d_in[3];
    const float* bpool = (const float*)d_in[4];
    const float* mlp_w = (const float*)d_in[5];
    const float* mlp_b = (const float*)d_in[6];
    float* out = (float*)d_out;

    cudaFuncSetAttribute(epilogue_kernel,
                         cudaFuncAttributeMaxDynamicSharedMemorySize, EPI_SMEM);

    float *pA, *pS2, *pPT, *pXr, *pG1, *pG2, *pD1, *pD2;
    cudaGetSymbolAddress((void**)&pA,  g_A);
    cudaGetSymbolAddress((void**)&pS2, g_S2);
    cudaGetSymbolAddress((void**)&pPT, g_PT);
    cudaGetSymbolAddress((void**)&pXr, g_Xr);
    cudaGetSymbolAddress((void**)&pG1, g_G1);
    cudaGetSymbolAddress((void**)&pG2, g_G2);
    cudaGetSymbolAddress((void**)&pD1, g_D1);
    cudaGetSymbolAddress((void**)&pD2, g_D2);

    // small precompute
    compute_A_kernel<<<Nn, 256>>>(emb);
    transpose_X_kernel<<<(Nn*1024)/256, 256>>>(x);
    transpose_P_kernel<<<dim3(Nn/32, Nn/32), dim3(32, 8)>>>(sup);

    // S2 = 2*(A@A) - I
    gemm_f32<<<dim3(Nn/128, Nn/128), 256>>>(Nn, Nn, Nn, 2.f, pA, pA, pS2, -1.f);

    // big GEMMs [2048,2048] @ [2048,12288]
    dim3 gBig(MC/128, Nn/128);
    gemm_f32<<<gBig, 256>>>(Nn, MC, Nn, 1.f, pA,  pXr, pG1, 0.f);
    gemm_f32<<<gBig, 256>>>(Nn, MC, Nn, 1.f, pS2, pXr, pG2, 0.f);
    gemm_f32<<<gBig, 256>>>(Nn, MC, Nn, 1.f, pPT, pXr, pD1, 0.f);
    gemm_f32<<<gBig, 256>>>(Nn, MC, Nn, 1.f, pPT, pD1, pD2, 0.f);

    // epilogues write both outputs
    epilogue_kernel<<<Nn, 256, EPI_SMEM>>>(emb, wpool, bpool, out, 0);
    epilogue_kernel<<<Nn, 256, EPI_SMEM>>>(emb, mlp_w, mlp_b, out, 1);
}

// round 6
// speedup vs baseline: 2.1866x; 2.1866x over previous
#include <cuda_runtime.h>
#include <cstdint>

// ---------------- problem constants ----------------
#define Nn   2048
#define Bb   16
#define Cc   64
#define Tt   12
#define Ee   10
#define Oo   64
#define MC   (Bb*Cc*Tt)        // 12288
#define NT   (Nn*Tt)           // 24576
#define ONT  (Oo*Nn*Tt)        // 1572864
#define XAV_SIZE (Bb*ONT)      // 25165824 floats

// ---------------- scratch (device globals) ----------------
__device__ float g_A [Nn*Nn];
__device__ float g_S2[Nn*Nn];
__device__ float g_PT[Nn*Nn];
__device__ float g_Xr[(size_t)Nn*MC];   // [node][12288]
__device__ float g_G1[(size_t)Nn*MC];
__device__ float g_G2[(size_t)Nn*MC];
__device__ float g_D1[(size_t)Nn*MC];
__device__ float g_D2[(size_t)Nn*MC];

// ---------------- helpers ----------------
__device__ __forceinline__ uint32_t f2tf32(float f){
    uint32_t u; asm("cvt.rna.tf32.f32 %0, %1;" : "=r"(u) : "f"(f)); return u;
}
__device__ __forceinline__ unsigned long long pack_dup(float a){
    unsigned long long r; asm("mov.b64 %0, {%1, %1};" : "=l"(r) : "f"(a)); return r;
}
__device__ __forceinline__ void fma2(unsigned long long &acc,
                                     unsigned long long a, unsigned long long b){
    asm("fma.rn.f32x2 %0, %1, %2, %0;" : "+l"(acc) : "l"(a), "l"(b));
}
__device__ __forceinline__ void mma_tf32(float* d,
    uint32_t a0, uint32_t a1, uint32_t a2, uint32_t a3,
    uint32_t b0, uint32_t b1)
{
    asm volatile(
        "mma.sync.aligned.m16n8k8.row.col.f32.tf32.tf32.f32 "
        "{%0,%1,%2,%3}, {%4,%5,%6,%7}, {%8,%9}, {%0,%1,%2,%3};"
        : "+f"(d[0]), "+f"(d[1]), "+f"(d[2]), "+f"(d[3])
        : "r"(a0), "r"(a1), "r"(a2), "r"(a3), "r"(b0), "r"(b1));
}

// ---------------- A = rowsoftmax(relu(E E^T)) ----------------
__global__ __launch_bounds__(256) void compute_A_kernel(const float* __restrict__ emb)
{
    __shared__ float row[Nn];
    __shared__ float red[256];
    const int n = blockIdx.x, tid = threadIdx.x;
    float e[Ee];
#pragma unroll
    for (int d = 0; d < Ee; d++) e[d] = emb[n*Ee + d];
    float lmax = -1e30f;
    for (int m = tid; m < Nn; m += 256){
        float s = 0.f;
#pragma unroll
        for (int d = 0; d < Ee; d++) s += e[d] * emb[m*Ee + d];
        s = fmaxf(s, 0.f);
        row[m] = s; lmax = fmaxf(lmax, s);
    }
    red[tid] = lmax; __syncthreads();
    for (int s = 128; s > 0; s >>= 1){ if (tid < s) red[tid] = fmaxf(red[tid], red[tid+s]); __syncthreads(); }
    const float mx = red[0]; __syncthreads();
    float lsum = 0.f;
    for (int m = tid; m < Nn; m += 256){ float v = expf(row[m] - mx); row[m] = v; lsum += v; }
    red[tid] = lsum; __syncthreads();
    for (int s = 128; s > 0; s >>= 1){ if (tid < s) red[tid] += red[tid+s]; __syncthreads(); }
    const float inv = 1.f / red[0];
    for (int m = tid; m < Nn; m += 256) g_A[(size_t)n*Nn + m] = row[m] * inv;
}

// ---------------- x[B,C,N,T] -> Xr[N][bc*12+t] ----------------
__global__ __launch_bounds__(256) void transpose_X_kernel(const float* __restrict__ x)
{
    int g  = blockIdx.x * 256 + threadIdx.x;
    int n  = g >> 10;
    int bc = g & 1023;
    const float4* src = (const float4*)(x + ((size_t)bc*Nn + n) * Tt);
    float4*       dst = (float4*)(g_Xr + (size_t)n*MC + (size_t)bc*Tt);
    dst[0] = src[0]; dst[1] = src[1]; dst[2] = src[2];
}

// ---------------- PT[w][v] = support[v][w] ----------------
__global__ void transpose2k_kernel(const float* __restrict__ S, float* __restrict__ D)
{
    __shared__ float tile[32][33];
    const int x0 = blockIdx.x*32, y0 = blockIdx.y*32;
    const int tx = threadIdx.x, ty = threadIdx.y;     // (32,8)
#pragma unroll
    for (int j = 0; j < 4; j++)
        tile[ty + j*8][tx] = S[(size_t)(y0 + ty + j*8)*Nn + x0 + tx];
    __syncthreads();
#pragma unroll
    for (int j = 0; j < 4; j++)
        D[(size_t)(x0 + ty + j*8)*Nn + y0 + tx] = tile[tx][ty + j*8];
}

// ---------------- tf32 mma.sync GEMM ----------------
// C[m][n] = alpha * sum_k A[m][k] * B[k][n]  (+ diagAdd on the diagonal)
// A row-major [2048 x 2048], B row-major [2048 x Ncols].
// CTA tile 128x128, BK=16, 8 warps in 4(m) x 2(n), warp tile 32x64 via m16n8k8.
#define SA 20     // A smem row stride (16 + 4 pad) -> conflict-free fragment loads
#define SB 136    // B smem row stride (128 + 8 pad)

__global__ __launch_bounds__(256, 2) void mma_gemm(
    int Ncols, float alpha,
    const float* __restrict__ A,
    const float* __restrict__ B,
    float* __restrict__ C, float diagAdd)
{
    __shared__ uint32_t As[2][128*SA];
    __shared__ uint32_t Bs[2][16*SB];

    const int tid  = threadIdx.x;
    const int lane = tid & 31;
    const int wid  = tid >> 5;
    const int wm   = wid >> 1;          // 0..3  -> 32 rows
    const int wn   = wid & 1;           // 0..1  -> 64 cols
    const int gy   = lane >> 2;         // 0..7
    const int gx   = lane & 3;          // 0..3

    const int nBase = blockIdx.x * 128;
    const int mBase = blockIdx.y * 128;

    // global load mapping
    const int arow = tid >> 1;               // 0..127
    const int ak   = (tid & 1) * 8;          // 0 or 8
    const int brow = tid >> 4;               // 0..15
    const int bcol = (tid & 15) * 8;         // 0..120

    const float* gA = A + (size_t)(mBase + arow)*2048 + ak;
    const float* gB = B + (size_t)brow*Ncols + nBase + bcol;

    float4 ra[2], rb[2];
#pragma unroll
    for (int i = 0; i < 2; i++){
        ra[i] = ((const float4*)gA)[i];
        rb[i] = ((const float4*)gB)[i];
    }
    // store tile 0
#pragma unroll
    for (int i = 0; i < 2; i++){
        *(uint4*)&As[0][arow*SA + ak + 4*i] =
            make_uint4(f2tf32(ra[i].x), f2tf32(ra[i].y), f2tf32(ra[i].z), f2tf32(ra[i].w));
        *(uint4*)&Bs[0][brow*SB + bcol + 4*i] =
            make_uint4(f2tf32(rb[i].x), f2tf32(rb[i].y), f2tf32(rb[i].z), f2tf32(rb[i].w));
    }
    __syncthreads();

    float acc[2][8][4];
#pragma unroll
    for (int mt = 0; mt < 2; mt++)
#pragma unroll
        for (int nt = 0; nt < 8; nt++)
#pragma unroll
            for (int r = 0; r < 4; r++) acc[mt][nt][r] = 0.f;

    const int NKT = 2048 / 16;   // 128 k-tiles
    for (int kt = 0; kt < NKT; kt++){
        const int s = kt & 1;
        const bool more = (kt + 1 < NKT);
        if (more){
            const float* pa = gA + (kt+1)*16;
            const float* pb = gB + (size_t)(kt+1)*16*Ncols;
#pragma unroll
            for (int i = 0; i < 2; i++){
                ra[i] = ((const float4*)pa)[i];
                rb[i] = ((const float4*)pb)[i];
            }
        }
        const uint32_t* Ap = As[s];
        const uint32_t* Bp = Bs[s];
#pragma unroll
        for (int ks = 0; ks < 2; ks++){
            const int k = ks * 8;
            uint32_t a[2][4];
#pragma unroll
            for (int mt = 0; mt < 2; mt++){
                const int rbase = wm*32 + mt*16;
                a[mt][0] = Ap[(rbase + gy    )*SA + k + gx    ];
                a[mt][1] = Ap[(rbase + gy + 8)*SA + k + gx    ];
                a[mt][2] = Ap[(rbase + gy    )*SA + k + gx + 4];
                a[mt][3] = Ap[(rbase + gy + 8)*SA + k + gx + 4];
            }
#pragma unroll
            for (int nt = 0; nt < 8; nt++){
                const int nb = wn*64 + nt*8 + gy;
                uint32_t b0 = Bp[(k + gx    )*SB + nb];
                uint32_t b1 = Bp[(k + gx + 4)*SB + nb];
                mma_tf32(acc[0][nt], a[0][0], a[0][1], a[0][2], a[0][3], b0, b1);
                mma_tf32(acc[1][nt], a[1][0], a[1][1], a[1][2], a[1][3], b0, b1);
            }
        }
        if (more){
            const int ns = s ^ 1;
#pragma unroll
            for (int i = 0; i < 2; i++){
                *(uint4*)&As[ns][arow*SA + ak + 4*i] =
                    make_uint4(f2tf32(ra[i].x), f2tf32(ra[i].y), f2tf32(ra[i].z), f2tf32(ra[i].w));
                *(uint4*)&Bs[ns][brow*SB + bcol + 4*i] =
                    make_uint4(f2tf32(rb[i].x), f2tf32(rb[i].y), f2tf32(rb[i].z), f2tf32(rb[i].w));
            }
            __syncthreads();
        }
    }

    // writeout
#pragma unroll
    for (int mt = 0; mt < 2; mt++){
#pragma unroll
        for (int nt = 0; nt < 8; nt++){
            const int row0 = mBase + wm*32 + mt*16 + gy;
            const int col0 = nBase + wn*64 + nt*8 + gx*2;
            float v0 = acc[mt][nt][0] * alpha;
            float v1 = acc[mt][nt][1] * alpha;
            float v2 = acc[mt][nt][2] * alpha;
            float v3 = acc[mt][nt][3] * alpha;
            if (diagAdd != 0.f){
                if (row0     == col0    ) v0 += diagAdd;
                if (row0     == col0 + 1) v1 += diagAdd;
                if (row0 + 8 == col0    ) v2 += diagAdd;
                if (row0 + 8 == col0 + 1) v3 += diagAdd;
            }
            *(float2*)(C + (size_t)row0    *Ncols + col0) = make_float2(v0, v1);
            *(float2*)(C + (size_t)(row0+8)*Ncols + col0) = make_float2(v2, v3);
        }
    }
}

// ---------------- per-node epilogue (f32x2 accumulators) ----------------
__global__ __launch_bounds__(256) void epilogue_kernel(
    const float* __restrict__ emb,
    const float* __restrict__ wsrc,
    const float* __restrict__ bsrc,
    float* __restrict__ out, int mode)
{
    extern __shared__ float sm[];
    float* sIn = sm;                 // 3*MC
    float* sW  = sm + 3*MC;          // 12288
    float* sB  = sW + 12288;         // 64
    const int n = blockIdx.x, tid = threadIdx.x;

    const float* s0 = g_Xr;
    const float* s1 = (mode == 0) ? g_G1 : g_D1;
    const float* s2 = (mode == 0) ? g_G2 : g_D2;
    const size_t off = (size_t)n * MC;

    for (int i = tid; i < MC/4; i += 256){
        ((float4*)sIn)[i]          = ((const float4*)(s0 + off))[i];
        ((float4*)(sIn +   MC))[i] = ((const float4*)(s1 + off))[i];
        ((float4*)(sIn + 2*MC))[i] = ((const float4*)(s2 + off))[i];
    }
    if (mode == 0){
        float e[Ee];
#pragma unroll
        for (int d = 0; d < Ee; d++) e[d] = emb[n*Ee + d];
        for (int i = tid; i < 12288; i += 256){
            float s = 0.f;
#pragma unroll
            for (int d = 0; d < Ee; d++) s += e[d] * wsrc[d*12288 + i];
            sW[i] = s;
        }
        if (tid < Oo){
            float s = 0.f;
#pragma unroll
            for (int d = 0; d < Ee; d++) s += e[d] * bsrc[d*Oo + tid];
            sB[tid] = s;
        }
    } else {
        for (int i = tid; i < 12288; i += 256) sW[i] = wsrc[i];
        if (tid < Oo) sB[tid] = bsrc[tid];
    }
    __syncthreads();

    const int ty = tid >> 4, tx = tid & 15;
    const int oBase = ty * 4;
    int offr[12], bArr[12], tArr[12];
#pragma unroll
    for (int i = 0; i < 12; i++){
        int r = tx + 16*i;
        int b = r / 12, t = r - b*12;
        offr[i] = b*(Cc*Tt) + t;
        bArr[i] = b; tArr[i] = t;
    }

    unsigned long long acc[12][2];
#pragma unroll
    for (int i = 0; i < 12; i++){ acc[i][0] = 0ULL; acc[i][1] = 0ULL; }

    for (int kc = 0; kc < 192; kc++){
        const int k = kc >> 6;
        const int c = kc & 63;
        const float* src = sIn + k*MC + c*Tt;
        const unsigned long long* wp = (const unsigned long long*)(sW + kc*64 + oBase);
        unsigned long long w01 = wp[0], w23 = wp[1];
#pragma unroll
        for (int i = 0; i < 12; i++){
            unsigned long long ap = pack_dup(src[offr[i]]);
            fma2(acc[i][0], ap, w01);
            fma2(acc[i][1], ap, w23);
        }
    }

    float* outBase = out + (mode ? (size_t)XAV_SIZE : 0);
#pragma unroll
    for (int i = 0; i < 12; i++){
        const int b = bArr[i], t = tArr[i];
        const size_t p = (size_t)b*ONT + (size_t)n*Tt + t;
        float2 f0 = *reinterpret_cast<float2*>(&acc[i][0]);
        float2 f1 = *reinterpret_cast<float2*>(&acc[i][1]);
        outBase[p + (size_t)(oBase+0)*NT] = f0.x + sB[oBase+0];
        outBase[p + (size_t)(oBase+1)*NT] = f0.y + sB[oBase+1];
        outBase[p + (size_t)(oBase+2)*NT] = f1.x + sB[oBase+2];
        outBase[p + (size_t)(oBase+3)*NT] = f1.y + sB[oBase+3];
    }
}

// ---------------- launch ----------------
#define EPI_SMEM ((3*MC + 12288 + 64) * (int)sizeof(float))

extern "C" void kernel_launch(void* const* d_in, const int* in_sizes, int n_in,
                              void* d_out, int out_size)
{
    const float* x     = (const float*)d_in[0];
    const float* emb   = (const float*)d_in[1];
    const float* sup   = (const float*)d_in[2];
    const float* wpool = (const float*)d_in[3];
    const float* bpool = (const float*)d_in[4];
    const float* mlp_w = (const float*)d_in[5];
    const float* mlp_b = (const float*)d_in[6];
    float* out = (float*)d_out;

    cudaFuncSetAttribute(epilogue_kernel, cudaFuncAttributeMaxDynamicSharedMemorySize, EPI_SMEM);

    float *pA, *pS2, *pPT, *pXr, *pG1, *pG2, *pD1, *pD2;
    cudaGetSymbolAddress((void**)&pA,  g_A);
    cudaGetSymbolAddress((void**)&pS2, g_S2);
    cudaGetSymbolAddress((void**)&pPT, g_PT);
    cudaGetSymbolAddress((void**)&pXr, g_Xr);
    cudaGetSymbolAddress((void**)&pG1, g_G1);
    cudaGetSymbolAddress((void**)&pG2, g_G2);
    cudaGetSymbolAddress((void**)&pD1, g_D1);
    cudaGetSymbolAddress((void**)&pD2, g_D2);

    // precompute
    compute_A_kernel<<<Nn, 256>>>(emb);
    transpose_X_kernel<<<(Nn*1024)/256, 256>>>(x);
    transpose2k_kernel<<<dim3(Nn/32, Nn/32), dim3(32, 8)>>>(sup, pPT);

    // S2 = 2*A@A - I   (B = A row-major is exactly what the kernel consumes)
    mma_gemm<<<dim3(16, 16), 256>>>(Nn, 2.f, pA, pA, pS2, -1.f);

    // big GEMMs [2048 x 12288], B row-major [k][n]
    dim3 gBig(MC/128, 16);
    mma_gemm<<<gBig, 256>>>(MC, 1.f, pA,  pXr, pG1, 0.f);
    mma_gemm<<<gBig, 256>>>(MC, 1.f, pS2, pXr, pG2, 0.f);
    mma_gemm<<<gBig, 256>>>(MC, 1.f, pPT, pXr, pD1, 0.f);
    mma_gemm<<<gBig, 256>>>(MC, 1.f, pPT, pD1, pD2, 0.f);

    // epilogues
    epilogue_kernel<<<Nn, 256, EPI_SMEM>>>(emb, wpool, bpool, out, 0);
    epilogue_kernel<<<Nn, 256, EPI_SMEM>>>(emb, mlp_w, mlp_b, out, 1);
}

// round 7
// speedup vs baseline: 2.4522x; 1.1215x over previous
#include <cuda_runtime.h>
#include <cstdint>

// ---------------- problem constants ----------------
#define Nn   2048
#define Bb   16
#define Cc   64
#define Tt   12
#define Ee   10
#define Oo   64
#define MC   (Bb*Cc*Tt)        // 12288
#define NT   (Nn*Tt)           // 24576
#define ONT  (Oo*Nn*Tt)        // 1572864
#define XAV_SIZE (Bb*ONT)      // 25165824 floats

// ---------------- scratch (device globals) ----------------
__device__ float g_A [Nn*Nn];
__device__ float g_PT[Nn*Nn];
__device__ float g_Xr[(size_t)Nn*MC];   // [node][12288], tf32-rounded
__device__ float g_G1[(size_t)Nn*MC];
__device__ float g_G2[(size_t)Nn*MC];
__device__ float g_D1[(size_t)Nn*MC];
__device__ float g_D2[(size_t)Nn*MC];

// ---------------- helpers ----------------
__device__ __forceinline__ uint32_t smem_u32(const void* p){
    uint32_t a;
    asm("{ .reg .u64 t; cvta.to.shared.u64 t, %1; cvt.u32.u64 %0, t; }" : "=r"(a) : "l"(p));
    return a;
}
__device__ __forceinline__ float rtf32(float f){
    uint32_t u; asm("cvt.rna.tf32.f32 %0, %1;" : "=r"(u) : "f"(f));
    return __uint_as_float(u);
}
__device__ __forceinline__ unsigned long long pack_dup(float a){
    unsigned long long r; asm("mov.b64 %0, {%1, %1};" : "=l"(r) : "f"(a)); return r;
}
__device__ __forceinline__ void fma2(unsigned long long &acc,
                                     unsigned long long a, unsigned long long b){
    asm("fma.rn.f32x2 %0, %1, %2, %0;" : "+l"(acc) : "l"(a), "l"(b));
}
__device__ __forceinline__ void mma_tf32(float* d,
    uint32_t a0, uint32_t a1, uint32_t a2, uint32_t a3,
    uint32_t b0, uint32_t b1)
{
    asm volatile(
        "mma.sync.aligned.m16n8k8.row.col.f32.tf32.tf32.f32 "
        "{%0,%1,%2,%3}, {%4,%5,%6,%7}, {%8,%9}, {%0,%1,%2,%3};"
        : "+f"(d[0]), "+f"(d[1]), "+f"(d[2]), "+f"(d[3])
        : "r"(a0), "r"(a1), "r"(a2), "r"(a3), "r"(b0), "r"(b1));
}
__device__ __forceinline__ void cp16(uint32_t d, const float* s){
    asm volatile("cp.async.cg.shared.global [%0], [%1], 16;" :: "r"(d), "l"(s));
}
#define CP_COMMIT() asm volatile("cp.async.commit_group;" ::: "memory")
#define CP_WAIT2()  asm volatile("cp.async.wait_group 2;" ::: "memory")

// ---------------- A = rowsoftmax(relu(E E^T)) , tf32-rounded ----------------
__global__ __launch_bounds__(256) void compute_A_kernel(const float* __restrict__ emb)
{
    __shared__ float row[Nn];
    __shared__ float red[256];
    const int n = blockIdx.x, tid = threadIdx.x;
    float e[Ee];
#pragma unroll
    for (int d = 0; d < Ee; d++) e[d] = emb[n*Ee + d];
    float lmax = -1e30f;
    for (int m = tid; m < Nn; m += 256){
        float s = 0.f;
#pragma unroll
        for (int d = 0; d < Ee; d++) s += e[d] * emb[m*Ee + d];
        s = fmaxf(s, 0.f);
        row[m] = s; lmax = fmaxf(lmax, s);
    }
    red[tid] = lmax; __syncthreads();
    for (int s = 128; s > 0; s >>= 1){ if (tid < s) red[tid] = fmaxf(red[tid], red[tid+s]); __syncthreads(); }
    const float mx = red[0]; __syncthreads();
    float lsum = 0.f;
    for (int m = tid; m < Nn; m += 256){ float v = expf(row[m] - mx); row[m] = v; lsum += v; }
    red[tid] = lsum; __syncthreads();
    for (int s = 128; s > 0; s >>= 1){ if (tid < s) red[tid] += red[tid+s]; __syncthreads(); }
    const float inv = 1.f / red[0];
    for (int m = tid; m < Nn; m += 256)
        g_A[(size_t)n*Nn + m] = rtf32(row[m] * inv);
}

// ---------------- x[B,C,N,T] -> Xr[N][bc*12+t] (tf32-rounded) ----------------
__global__ __launch_bounds__(256) void transpose_X_kernel(const float* __restrict__ x)
{
    int g  = blockIdx.x * 256 + threadIdx.x;
    int n  = g >> 10;
    int bc = g & 1023;
    const float4* src = (const float4*)(x + ((size_t)bc*Nn + n) * Tt);
    float4*       dst = (float4*)(g_Xr + (size_t)n*MC + (size_t)bc*Tt);
#pragma unroll
    for (int i = 0; i < 3; i++){
        float4 v = src[i];
        dst[i] = make_float4(rtf32(v.x), rtf32(v.y), rtf32(v.z), rtf32(v.w));
    }
}

// ---------------- PT[w][v] = support[v][w] (tf32-rounded) ----------------
__global__ void transpose2k_kernel(const float* __restrict__ S, float* __restrict__ D)
{
    __shared__ float tile[32][33];
    const int x0 = blockIdx.x*32, y0 = blockIdx.y*32;
    const int tx = threadIdx.x, ty = threadIdx.y;     // (32,8)
#pragma unroll
    for (int j = 0; j < 4; j++)
        tile[ty + j*8][tx] = S[(size_t)(y0 + ty + j*8)*Nn + x0 + tx];
    __syncthreads();
#pragma unroll
    for (int j = 0; j < 4; j++)
        D[(size_t)(x0 + ty + j*8)*Nn + y0 + tx] = rtf32(tile[tx][ty + j*8]);
}

// ---------------- tf32 mma.sync GEMM, 4-stage cp.async pipeline ----------------
// C[m][n] = alpha * sum_k A[m][k]*B[k][n] + beta*Res[m][n]   (Res optional)
// A [2048 x 2048] row-major (tf32 values), B [2048 x Ncols] row-major (tf32 values).
// CTA 128x128, BK=16, 8 warps 4(m) x 2(n), warp 32x64 via m16n8k8.
#define SA 20                       // A smem row stride (words)
#define SB 136                      // B smem row stride (words)
#define A_STAGE_W (128*SA)          // 2560 words
#define B_STAGE_W (16*SB)           // 2176 words
#define STAGE_W   (A_STAGE_W + B_STAGE_W)
#define STAGE_BYTES (STAGE_W*4)     // 18944
#define GEMM_SMEM (4*STAGE_BYTES)   // 75776

__global__ __launch_bounds__(256, 2) void mma_gemm(
    int Ncols, float alpha,
    const float* __restrict__ A,
    const float* __restrict__ B,
    float* __restrict__ C,
    const float* __restrict__ Res, float beta, int roundOut)
{
    extern __shared__ __align__(16) uint32_t smw[];
    const uint32_t sbase = smem_u32(smw);

    const int tid  = threadIdx.x;
    const int lane = tid & 31;
    const int wid  = tid >> 5;
    const int wm   = wid >> 1;          // 0..3
    const int wn   = wid & 1;           // 0..1
    const int gy   = lane >> 2;         // 0..7
    const int gx   = lane & 3;          // 0..3

    const int nBase = blockIdx.x * 128;
    const int mBase = blockIdx.y * 128;

    // cp.async mapping: 4 x 16B per thread per stage (2 A, 2 B)
    const int aRow = tid >> 1;               // 0..127
    const int aK0  = (tid & 1) * 8;          // 0 or 8
    const int bKr  = tid >> 4;               // 0..15
    const int bN0  = (tid & 15) * 8;         // 0..120
    const float* aSrc = A + (size_t)(mBase + aRow)*2048 + aK0;
    const float* bSrc = B + (size_t)bKr*Ncols + nBase + bN0;
    const uint32_t aDst = (uint32_t)(aRow*SA + aK0) * 4;
    const uint32_t bDst = (uint32_t)(A_STAGE_W + bKr*SB + bN0) * 4;

#define ISSUE_STAGE(kt_) do { \
        uint32_t sb_ = sbase + ((kt_) & 3) * STAGE_BYTES; \
        const float* as_ = aSrc + (kt_)*16; \
        const float* bs_ = bSrc + (size_t)(kt_)*16*Ncols; \
        cp16(sb_ + aDst,      as_); \
        cp16(sb_ + aDst + 16, as_ + 4); \
        cp16(sb_ + bDst,      bs_); \
        cp16(sb_ + bDst + 16, bs_ + 4); \
    } while(0)

    ISSUE_STAGE(0); CP_COMMIT();
    ISSUE_STAGE(1); CP_COMMIT();
    ISSUE_STAGE(2); CP_COMMIT();

    float acc[2][8][4];
#pragma unroll
    for (int mt = 0; mt < 2; mt++)
#pragma unroll
        for (int nt = 0; nt < 8; nt++)
#pragma unroll
            for (int r = 0; r < 4; r++) acc[mt][nt][r] = 0.f;

    const int NKT = 2048 / 16;   // 128
    for (int kt = 0; kt < NKT; kt++){
        CP_WAIT2();
        __syncthreads();
        const int pf = kt + 3;
        if (pf < NKT) ISSUE_STAGE(pf);
        CP_COMMIT();

        const uint32_t* Ap = smw + (kt & 3) * STAGE_W;
        const uint32_t* Bp = Ap + A_STAGE_W;
#pragma unroll
        for (int ks = 0; ks < 2; ks++){
            const int k = ks * 8;
            uint32_t a[2][4];
#pragma unroll
            for (int mt = 0; mt < 2; mt++){
                const int rbase = wm*32 + mt*16;
                a[mt][0] = Ap[(rbase + gy    )*SA + k + gx    ];
                a[mt][1] = Ap[(rbase + gy + 8)*SA + k + gx    ];
                a[mt][2] = Ap[(rbase + gy    )*SA + k + gx + 4];
                a[mt][3] = Ap[(rbase + gy + 8)*SA + k + gx + 4];
            }
#pragma unroll
            for (int nt = 0; nt < 8; nt++){
                const int nb = wn*64 + nt*8 + gy;
                uint32_t b0 = Bp[(k + gx    )*SB + nb];
                uint32_t b1 = Bp[(k + gx + 4)*SB + nb];
                mma_tf32(acc[0][nt], a[0][0], a[0][1], a[0][2], a[0][3], b0, b1);
                mma_tf32(acc[1][nt], a[1][0], a[1][1], a[1][2], a[1][3], b0, b1);
            }
        }
    }
#undef ISSUE_STAGE

    // writeout
#pragma unroll
    for (int mt = 0; mt < 2; mt++){
#pragma unroll
        for (int nt = 0; nt < 8; nt++){
            const int row0 = mBase + wm*32 + mt*16 + gy;
            const int col0 = nBase + wn*64 + nt*8 + gx*2;
            float v0 = acc[mt][nt][0] * alpha;
            float v1 = acc[mt][nt][1] * alpha;
            float v2 = acc[mt][nt][2] * alpha;
            float v3 = acc[mt][nt][3] * alpha;
            if (Res){
                float2 r0 = *(const float2*)(Res + (size_t)row0    *Ncols + col0);
                float2 r1 = *(const float2*)(Res + (size_t)(row0+8)*Ncols + col0);
                v0 += beta * r0.x; v1 += beta * r0.y;
                v2 += beta * r1.x; v3 += beta * r1.y;
            }
            if (roundOut){
                v0 = rtf32(v0); v1 = rtf32(v1); v2 = rtf32(v2); v3 = rtf32(v3);
            }
            *(float2*)(C + (size_t)row0    *Ncols + col0) = make_float2(v0, v1);
            *(float2*)(C + (size_t)(row0+8)*Ncols + col0) = make_float2(v2, v3);
        }
    }
}

// ---------------- per-node epilogue (f32x2 accumulators) ----------------
__global__ __launch_bounds__(256) void epilogue_kernel(
    const float* __restrict__ emb,
    const float* __restrict__ wsrc,
    const float* __restrict__ bsrc,
    float* __restrict__ out, int mode)
{
    extern __shared__ float sm[];
    float* sIn = sm;                 // 3*MC
    float* sW  = sm + 3*MC;          // 12288
    float* sB  = sW + 12288;         // 64
    const int n = blockIdx.x, tid = threadIdx.x;

    const float* s0 = g_Xr;
    const float* s1 = (mode == 0) ? g_G1 : g_D1;
    const float* s2 = (mode == 0) ? g_G2 : g_D2;
    const size_t off = (size_t)n * MC;

    for (int i = tid; i < MC/4; i += 256){
        ((float4*)sIn)[i]          = ((const float4*)(s0 + off))[i];
        ((float4*)(sIn +   MC))[i] = ((const float4*)(s1 + off))[i];
        ((float4*)(sIn + 2*MC))[i] = ((const float4*)(s2 + off))[i];
    }
    if (mode == 0){
        float e[Ee];
#pragma unroll
        for (int d = 0; d < Ee; d++) e[d] = emb[n*Ee + d];
        for (int i = tid; i < 12288; i += 256){
            float s = 0.f;
#pragma unroll
            for (int d = 0; d < Ee; d++) s += e[d] * wsrc[d*12288 + i];
            sW[i] = s;
        }
        if (tid < Oo){
            float s = 0.f;
#pragma unroll
            for (int d = 0; d < Ee; d++) s += e[d] * bsrc[d*Oo + tid];
            sB[tid] = s;
        }
    } else {
        for (int i = tid; i < 12288; i += 256) sW[i] = wsrc[i];
        if (tid < Oo) sB[tid] = bsrc[tid];
    }
    __syncthreads();

    const int ty = tid >> 4, tx = tid & 15;
    const int oBase = ty * 4;
    int offr[12], bArr[12], tArr[12];
#pragma unroll
    for (int i = 0; i < 12; i++){
        int r = tx + 16*i;
        int b = r / 12, t = r - b*12;
        offr[i] = b*(Cc*Tt) + t;
        bArr[i] = b; tArr[i] = t;
    }

    unsigned long long acc[12][2];
#pragma unroll
    for (int i = 0; i < 12; i++){ acc[i][0] = 0ULL; acc[i][1] = 0ULL; }

    for (int kc = 0; kc < 192; kc++){
        const int k = kc >> 6;
        const int c = kc & 63;
        const float* src = sIn + k*MC + c*Tt;
        const unsigned long long* wp = (const unsigned long long*)(sW + kc*64 + oBase);
        unsigned long long w01 = wp[0], w23 = wp[1];
#pragma unroll
        for (int i = 0; i < 12; i++){
            unsigned long long ap = pack_dup(src[offr[i]]);
            fma2(acc[i][0], ap, w01);
            fma2(acc[i][1], ap, w23);
        }
    }

    float* outBase = out + (mode ? (size_t)XAV_SIZE : 0);
#pragma unroll
    for (int i = 0; i < 12; i++){
        const int b = bArr[i], t = tArr[i];
        const size_t p = (size_t)b*ONT + (size_t)n*Tt + t;
        float2 f0 = *reinterpret_cast<float2*>(&acc[i][0]);
        float2 f1 = *reinterpret_cast<float2*>(&acc[i][1]);
        outBase[p + (size_t)(oBase+0)*NT] = f0.x + sB[oBase+0];
        outBase[p + (size_t)(oBase+1)*NT] = f0.y + sB[oBase+1];
        outBase[p + (size_t)(oBase+2)*NT] = f1.x + sB[oBase+2];
        outBase[p + (size_t)(oBase+3)*NT] = f1.y + sB[oBase+3];
    }
}

// ---------------- launch ----------------
#define EPI_SMEM ((3*MC + 12288 + 64) * (int)sizeof(float))

extern "C" void kernel_launch(void* const* d_in, const int* in_sizes, int n_in,
                              void* d_out, int out_size)
{
    const float* x     = (const float*)d_in[0];
    const float* emb   = (const float*)d_in[1];
    const float* sup   = (const float*)d_in[2];
    const float* wpool = (const float*)d_in[3];
    const float* bpool = (const float*)d_in[4];
    const float* mlp_w = (const float*)d_in[5];
    const float* mlp_b = (const float*)d_in[6];
    float* out = (float*)d_out;

    cudaFuncSetAttribute(epilogue_kernel, cudaFuncAttributeMaxDynamicSharedMemorySize, EPI_SMEM);
    cudaFuncSetAttribute(mma_gemm, cudaFuncAttributeMaxDynamicSharedMemorySize, GEMM_SMEM);

    float *pA, *pPT, *pXr, *pG1, *pG2, *pD1, *pD2;
    cudaGetSymbolAddress((void**)&pA,  g_A);
    cudaGetSymbolAddress((void**)&pPT, g_PT);
    cudaGetSymbolAddress((void**)&pXr, g_Xr);
    cudaGetSymbolAddress((void**)&pG1, g_G1);
    cudaGetSymbolAddress((void**)&pG2, g_G2);
    cudaGetSymbolAddress((void**)&pD1, g_D1);
    cudaGetSymbolAddress((void**)&pD2, g_D2);

    // precompute (all tf32-rounded at the producer)
    compute_A_kernel<<<Nn, 256>>>(emb);
    transpose_X_kernel<<<(Nn*1024)/256, 256>>>(x);
    transpose2k_kernel<<<dim3(Nn/32, Nn/32), dim3(32, 8)>>>(sup, pPT);

    // big GEMMs [2048 x 12288]
    dim3 gBig(MC/128, 16);
    // G1 = A @ Xr                (rounded: consumed by G2 GEMM)
    mma_gemm<<<gBig, 256, GEMM_SMEM>>>(MC, 1.f, pA, pXr, pG1, nullptr, 0.f, 1);
    // G2 = 2*A @ G1 - Xr         ( == (2A^2 - I) @ X )
    mma_gemm<<<gBig, 256, GEMM_SMEM>>>(MC, 2.f, pA, pG1, pG2, pXr, -1.f, 0);
    // D1 = PT @ Xr               (rounded: consumed by D2 GEMM)
    mma_gemm<<<gBig, 256, GEMM_SMEM>>>(MC, 1.f, pPT, pXr, pD1, nullptr, 0.f, 1);
    // D2 = PT @ D1
    mma_gemm<<<gBig, 256, GEMM_SMEM>>>(MC, 1.f, pPT, pD1, pD2, nullptr, 0.f, 0);

    // epilogues
    epilogue_kernel<<<Nn, 256, EPI_SMEM>>>(emb, wpool, bpool, out, 0);
    epilogue_kernel<<<Nn, 256, EPI_SMEM>>>(emb, mlp_w, mlp_b, out, 1);
}